// round 7
// baseline (speedup 1.0000x reference)
#include <cuda_runtime.h>
#include <cuda_bf16.h>
#include <math.h>
#include <stdint.h>

#define NMAX 100000
#define EMAX 1700000
#define FULLM 0xffffffffu

// Scratch: per-node P (cols 0..63, includes b1) and Q (cols 64..127). 51.2 MB.
__device__ float g_PQ[(size_t)NMAX * 128];
__device__ int2 g_edges[EMAX];    // packed (src, dst) as int32 (input order)
__device__ int2 g_sorted[EMAX];   // edges sorted (grouped) by dst
__device__ unsigned g_hist[NMAX];
__device__ unsigned g_cursor[NMAX];
__device__ int g_is64;

__device__ __forceinline__ uint32_t smem_u32(const void* p) {
    uint32_t a;
    asm("{ .reg .u64 t; cvta.to.shared.u64 t, %1; cvt.u32.u64 %0, t; }"
        : "=r"(a) : "l"(p));
    return a;
}

// m16n8k16 row.col f32 += bf16*bf16
__device__ __forceinline__ void mma16816(float* c, const uint32_t* a,
                                         const uint32_t* b) {
    asm volatile(
        "mma.sync.aligned.m16n8k16.row.col.f32.bf16.bf16.f32 "
        "{%0,%1,%2,%3}, {%4,%5,%6,%7}, {%8,%9}, {%0,%1,%2,%3};"
        : "+f"(c[0]), "+f"(c[1]), "+f"(c[2]), "+f"(c[3])
        : "r"(a[0]), "r"(a[1]), "r"(a[2]), "r"(a[3]), "r"(b[0]), "r"(b[1]));
}

__device__ __forceinline__ void ldmatrix_x4(uint32_t* r, uint32_t addr) {
    asm volatile(
        "ldmatrix.sync.aligned.m8n8.x4.shared.b16 {%0,%1,%2,%3}, [%4];"
        : "=r"(r[0]), "=r"(r[1]), "=r"(r[2]), "=r"(r[3]) : "r"(addr));
}

// ===========================================================================
// Detect int64 vs int32 edge_index (jax x64-disabled emits int32).
// ===========================================================================
__global__ void detect_kernel(const unsigned int* __restrict__ ei) {
    __shared__ int any;
    if (threadIdx.x == 0) any = 0;
    __syncthreads();
    if (ei[2 * threadIdx.x + 1] != 0u) any = 1;  // benign race
    __syncthreads();
    if (threadIdx.x == 0) g_is64 = (any == 0) ? 1 : 0;
}

__global__ void conv_edges_kernel(const void* __restrict__ eidx, int E) {
    int i = blockIdx.x * blockDim.x + threadIdx.x;
    if (i >= E) return;
    int s, d;
    if (g_is64) {
        const long long* e64 = (const long long*)eidx;
        s = (int)e64[i];
        d = (int)e64[E + i];
    } else {
        const int* e32 = (const int*)eidx;
        s = e32[i];
        d = e32[E + i];
    }
    g_edges[i] = make_int2(s, d);
}

// ===========================================================================
// Counting sort by dst: zero hist -> histogram -> exclusive scan -> scatter.
// ===========================================================================
__global__ void zero_hist_kernel(int N) {
    int i = blockIdx.x * blockDim.x + threadIdx.x;
    if (i < N) g_hist[i] = 0u;
}

__global__ void hist_kernel(int E) {
    int i = blockIdx.x * blockDim.x + threadIdx.x;
    if (i < E) atomicAdd(&g_hist[g_edges[i].y], 1u);
}

// Single-block exclusive scan over N counters -> g_cursor.
__global__ __launch_bounds__(1024) void scan_kernel(int N) {
    __shared__ unsigned wsum[32];
    __shared__ unsigned carry_s;
    int tid = threadIdx.x, lane = tid & 31, w = tid >> 5;
    if (tid == 0) carry_s = 0u;
    __syncthreads();
    for (int base = 0; base < N; base += 1024) {
        int i = base + tid;
        unsigned v = (i < N) ? g_hist[i] : 0u;
        unsigned x = v;
#pragma unroll
        for (int o = 1; o < 32; o <<= 1) {
            unsigned y = __shfl_up_sync(FULLM, x, o);
            if (lane >= o) x += y;
        }
        if (lane == 31) wsum[w] = x;
        __syncthreads();
        if (w == 0) {
            unsigned s = wsum[lane];
#pragma unroll
            for (int o = 1; o < 32; o <<= 1) {
                unsigned y = __shfl_up_sync(FULLM, s, o);
                if (lane >= o) s += y;
            }
            wsum[lane] = s;
        }
        __syncthreads();
        unsigned incl = x + (w > 0 ? wsum[w - 1] : 0u) + carry_s;
        if (i < N) g_cursor[i] = incl - v;
        __syncthreads();  // all carry_s reads done
        if (tid == 1023) carry_s = incl;
        __syncthreads();
    }
}

__global__ void scatter_kernel(int E) {
    int i = blockIdx.x * blockDim.x + threadIdx.x;
    if (i >= E) return;
    int2 sd = g_edges[i];
    unsigned pos = atomicAdd(&g_cursor[sd.y], 1u);
    g_sorted[pos] = sd;
}

// ===========================================================================
// Node kernel: PQ[n] = [ x@(W1a-W1b)+b1 | x@W1b ],  x = [feat(64) | xyz(3)]
// ===========================================================================
__global__ __launch_bounds__(256) void node_pq_kernel(
    const float* __restrict__ xyz, const float* __restrict__ feat,
    const float* __restrict__ W1, const float* __restrict__ b1, int N) {
    __shared__ float ws[67][128];
    __shared__ float xs[32][68];

    int tid = threadIdx.x;
    for (int i = tid; i < 67 * 128; i += 256) {
        int k = i >> 7, c = i & 127;
        float w1b = W1[(k + 67) * 64 + (c & 63)];
        ws[k][c] = (c < 64) ? (W1[k * 64 + c] - w1b) : w1b;
    }
    int n0 = blockIdx.x * 32;
    for (int i = tid; i < 32 * 67; i += 256) {
        int n = i / 67, k = i - n * 67;
        int gn = n0 + n;
        float v = 0.f;
        if (gn < N) v = (k < 64) ? feat[(size_t)gn * 64 + k]
                                 : xyz[(size_t)gn * 3 + (k - 64)];
        xs[n][k] = v;
    }
    __syncthreads();

    int cg = tid & 31, ng = tid >> 5;
    int c0 = cg * 4, nr = ng * 4;
    float acc[4][4];
#pragma unroll
    for (int i = 0; i < 4; i++)
#pragma unroll
        for (int j = 0; j < 4; j++)
            acc[i][j] = (c0 < 64) ? b1[c0 + j] : 0.f;

#pragma unroll 67
    for (int k = 0; k < 67; k++) {
        float4 w = *(const float4*)&ws[k][c0];
#pragma unroll
        for (int i = 0; i < 4; i++) {
            float xv = xs[nr + i][k];
            acc[i][0] = fmaf(xv, w.x, acc[i][0]);
            acc[i][1] = fmaf(xv, w.y, acc[i][1]);
            acc[i][2] = fmaf(xv, w.z, acc[i][2]);
            acc[i][3] = fmaf(xv, w.w, acc[i][3]);
        }
    }
#pragma unroll
    for (int i = 0; i < 4; i++) {
        int gn = n0 + nr + i;
        if (gn < N) {
            float4 v = make_float4(acc[i][0], acc[i][1], acc[i][2], acc[i][3]);
            *(float4*)&g_PQ[(size_t)gn * 128 + c0] = v;
        }
    }
}

// ===========================================================================
// Init output to -inf bits (vectorized); finalize -inf -> 0
// ===========================================================================
__global__ void init_kernel(uint4* __restrict__ out, int n4) {
    int i = blockIdx.x * blockDim.x + threadIdx.x;
    if (i < n4)
        out[i] = make_uint4(0xff800000u, 0xff800000u, 0xff800000u, 0xff800000u);
}

__global__ void finalize_kernel(uint4* __restrict__ out, int n4) {
    int i = blockIdx.x * blockDim.x + threadIdx.x;
    if (i >= n4) return;
    uint4 v = out[i];
    bool ch = false;
    if (v.x == 0xff800000u) { v.x = 0u; ch = true; }
    if (v.y == 0xff800000u) { v.y = 0u; ch = true; }
    if (v.z == 0xff800000u) { v.z = 0u; ch = true; }
    if (v.w == 0xff800000u) { v.w = 0u; ch = true; }
    if (ch) out[i] = v;
}

// ===========================================================================
// Float atomic max via int/uint ordering trick (no return -> RED, no stall).
// ===========================================================================
__device__ __forceinline__ void atomic_max_f(float* a, float v) {
    if (v >= 0.f)
        atomicMax((int*)a, __float_as_int(v));
    else
        atomicMin((unsigned int*)a, __float_as_uint(v));
}

// ===========================================================================
// Edge HMMA kernel, v4: sorted edges + register segmented reduction.
// Persistent CTAs, 128 threads = 4 independent warps, 4 CTAs/SM.
// Per warp-tile (32 edges, grouped by dst):
//   cooperative gather -> z = relu(P[dst]+Q[src]) -> bf16 hi/lo -> SMEM
//   Y = zh@Wh + zl@Wh + zh@Wl  (mma.sync m16n8k16, fp32 accum, b2 in C-init)
//   Epilogue: per (mt,nt) ballot-delimited dst-segments reduced in registers
//   (mask + 3-step shfl.xor butterfly), ONE unconditional RED per (seg,col).
// ===========================================================================
__global__ __launch_bounds__(128, 4) void edge_mma_kernel(
    const float* __restrict__ W2, const float* __restrict__ b2,
    float* __restrict__ out, int E) {
    __shared__ char zbuf[4][8192];   // per warp: hi 4KB + lo 4KB
    __shared__ char wtile[2][8192];  // W2^T hi, lo (64 rows n x 128B k)

    const int tid = threadIdx.x;
    const int lane = tid & 31;
    const int wid = tid >> 5;

    // ---- build swizzled W2^T hi/lo in SMEM (once per CTA) ----
    for (int i = tid; i < 64 * 64; i += 128) {
        int n = i >> 6, k = i & 63;
        float w = W2[k * 64 + n];
        __nv_bfloat16 h = __float2bfloat16(w);
        __nv_bfloat16 l = __float2bfloat16(w - __bfloat162float(h));
        uint32_t off = (uint32_t)n * 128 + (((uint32_t)(2 * k)) ^ ((uint32_t)(n & 7) << 4));
        *(__nv_bfloat16*)(&wtile[0][off]) = h;
        *(__nv_bfloat16*)(&wtile[1][off]) = l;
    }
    __syncthreads();

    const uint32_t zh_base = smem_u32(&zbuf[wid][0]);
    const uint32_t zl_base = zh_base + 4096;
    const uint32_t wh_base = smem_u32(&wtile[0][0]);
    const uint32_t wl_base = smem_u32(&wtile[1][0]);

    // B-frag ldmatrix lane addressing (covers ks pair per x4)
    const uint32_t brow = lane & 7;
    const uint32_t bswz = brow << 4;
    const uint32_t bpart = (((uint32_t)lane >> 3) & 1) * 16 + (((uint32_t)lane >> 4) & 1) * 32;
    const uint32_t boff0 = brow * 128 + (bpart ^ bswz);        // ks0,ks1
    const uint32_t boff1 = brow * 128 + ((bpart + 64) ^ bswz); // ks2,ks3

    // A-frag ldmatrix lane addressing
    const int am = lane >> 3, rowin = lane & 7;
    const uint32_t lswz = (uint32_t)rowin << 4;
    const uint32_t akb = (uint32_t)((am >> 1) << 4);
    const int arow_in = ((am & 1) << 3) + rowin;

    const int rsel = lane >> 2;
    const int colb = (lane & 3) * 2;

    // b2 pairs register-resident
    float2 b2v[8];
#pragma unroll
    for (int nt = 0; nt < 8; nt++)
        b2v[nt] = *(const float2*)(b2 + nt * 8 + colb);

    // cooperative-gather lane pieces
    const int sub = lane >> 4;               // which edge of the pair
    const int cq = lane & 15;                // column quad (4 floats)
    const uint32_t cbyte = (uint32_t)cq * 8; // byte offset in bf16 row

    const float NEG_INF = __int_as_float(0xff800000);

    const int T = (E + 31) >> 5;
    const int gw = blockIdx.x * 4 + wid;
    const int nw = gridDim.x * 4;

    if (gw >= T) return;

    int t = gw;
    int e0 = t * 32 + lane;
    int2 sd = g_sorted[(e0 < E) ? e0 : 0];

    for (; t < T; t += nw) {
        int e = t * 32 + lane;
        bool valid = (e < E);
        int mydst = valid ? sd.y : -1;

        // segment boundaries (dst-sorted: equal dst are contiguous)
        unsigned vmask = __ballot_sync(FULLM, valid);
        int prevd = __shfl_up_sync(FULLM, mydst, 1);
        bool flag = valid && (lane == 0 || mydst != prevd);
        unsigned segb = __ballot_sync(FULLM, flag);

        __syncwarp();  // prior tile's ldmatrix reads done before overwrite

        // ---- cooperative gather + relu + bf16 split -> SMEM ----
#pragma unroll 4
        for (int g = 0; g < 16; g++) {
            int esel = 2 * g + sub;
            int d = __shfl_sync(FULLM, sd.y, esel);
            int s = __shfl_sync(FULLM, sd.x, esel);
            float4 p = *((const float4*)(g_PQ + (size_t)d * 128) + cq);
            float4 q = *((const float4*)(g_PQ + (size_t)s * 128 + 64) + cq);
            float z0 = fmaxf(p.x + q.x, 0.f), z1 = fmaxf(p.y + q.y, 0.f);
            float z2 = fmaxf(p.z + q.z, 0.f), z3 = fmaxf(p.w + q.w, 0.f);
            __nv_bfloat162 h01 = __floats2bfloat162_rn(z0, z1);
            __nv_bfloat162 h23 = __floats2bfloat162_rn(z2, z3);
            __nv_bfloat162 l01 = __floats2bfloat162_rn(
                z0 - __bfloat162float(h01.x), z1 - __bfloat162float(h01.y));
            __nv_bfloat162 l23 = __floats2bfloat162_rn(
                z2 - __bfloat162float(h23.x), z3 - __bfloat162float(h23.y));
            uint32_t row = (uint32_t)(2 * g + sub);
            uint32_t off = row * 128 + (cbyte ^ ((row & 7) << 4));
            asm volatile("st.shared.v2.b32 [%0], {%1,%2};"
                         :: "r"(zh_base + off),
                            "r"(*(uint32_t*)&h01), "r"(*(uint32_t*)&h23));
            asm volatile("st.shared.v2.b32 [%0], {%1,%2};"
                         :: "r"(zl_base + off),
                            "r"(*(uint32_t*)&l01), "r"(*(uint32_t*)&l23));
        }
        __syncwarp();

        // ---- prefetch next tile's edge record (hides L2 latency) ----
        int tn = t + nw;
        if (tn < T) {
            int en = tn * 32 + lane;
            sd = g_sorted[(en < E) ? en : 0];
        }

#pragma unroll
        for (int mt = 0; mt < 2; mt++) {
            // A fragments for this 16-row slice (hi + lo, 4 k-steps)
            uint32_t ah[4][4], al[4][4];
            uint32_t rowb = (uint32_t)(mt * 16 + arow_in) * 128;
#pragma unroll
            for (int ks = 0; ks < 4; ks++) {
                uint32_t off = rowb + (((uint32_t)ks * 32 + akb) ^ lswz);
                ldmatrix_x4(ah[ks], zh_base + off);
                ldmatrix_x4(al[ks], zl_base + off);
            }

            // dst of this lane's two fragment rows
            int d0 = __shfl_sync(FULLM, mydst, mt * 16 + rsel);
            int d1 = __shfl_sync(FULLM, mydst, mt * 16 + 8 + rsel);

            // segments overlapping this mt half
            unsigned mtseg;
            if (mt == 0) {
                mtseg = segb & 0xFFFFu;
            } else {
                mtseg = segb & 0xFFFF0000u;
                unsigned lo = segb & 0xFFFFu;
                bool l16v = (vmask >> 16) & 1u;
                bool l16s = (segb >> 16) & 1u;
                if (l16v && !l16s && lo)
                    mtseg |= (1u << (31 - __clz(lo)));  // straddling segment
            }

#pragma unroll
            for (int nt = 0; nt < 8; nt++) {
                uint32_t bh[4][2], bl[4][2];
                uint32_t wb = (uint32_t)nt * 1024;
                ldmatrix_x4(&bh[0][0], wh_base + wb + boff0);
                ldmatrix_x4(&bh[2][0], wh_base + wb + boff1);
                ldmatrix_x4(&bl[0][0], wl_base + wb + boff0);
                ldmatrix_x4(&bl[2][0], wl_base + wb + boff1);

                float c[4] = {b2v[nt].x, b2v[nt].y, b2v[nt].x, b2v[nt].y};
#pragma unroll
                for (int ks = 0; ks < 4; ks++) mma16816(c, ah[ks], bh[ks]);
#pragma unroll
                for (int ks = 0; ks < 4; ks++) mma16816(c, al[ks], bh[ks]);
#pragma unroll
                for (int ks = 0; ks < 4; ks++) mma16816(c, ah[ks], bl[ks]);

                // ---- register segmented max + unconditional RED ----
                unsigned b = mtseg;
                while (b) {
                    int sl = __ffs(b) - 1;
                    b &= b - 1;
                    int D = __shfl_sync(FULLM, mydst, sl);
                    float m0 = NEG_INF, m1 = NEG_INF;
                    if (d0 == D) { m0 = c[0]; m1 = c[1]; }
                    if (d1 == D) { m0 = fmaxf(m0, c[2]); m1 = fmaxf(m1, c[3]); }
#pragma unroll
                    for (int o = 4; o <= 16; o <<= 1) {
                        m0 = fmaxf(m0, __shfl_xor_sync(FULLM, m0, o));
                        m1 = fmaxf(m1, __shfl_xor_sync(FULLM, m1, o));
                    }
                    if (lane < 4 && __float_as_uint(m0) != 0xff800000u) {
                        float* o = out + (size_t)D * 64 + nt * 8 + lane * 2;
                        atomic_max_f(o, m0);
                        atomic_max_f(o + 1, m1);
                    }
                }
            }
        }
    }
}

// ===========================================================================
// Inputs: [0]=xyz (N*3 f32), [1]=feat (N*64 f32), [2]=edge_index (2*E int),
//         [3]=W1 (134*64 f32), [4]=b1 (64), [5]=W2 (64*64), [6]=b2 (64)
// ===========================================================================
extern "C" void kernel_launch(void* const* d_in, const int* in_sizes, int n_in,
                              void* d_out, int out_size) {
    const float* xyz  = (const float*)d_in[0];
    const float* feat = (const float*)d_in[1];
    const void*  eidx = d_in[2];
    const float* W1   = (const float*)d_in[3];
    const float* b1   = (const float*)d_in[4];
    const float* W2   = (const float*)d_in[5];
    const float* b2   = (const float*)d_in[6];
    float* out = (float*)d_out;

    int N = in_sizes[0] / 3;
    int E = in_sizes[2] / 2;
    int outn = N * 64;
    int n4 = outn / 4;

    detect_kernel<<<1, 1024>>>((const unsigned int*)eidx);
    conv_edges_kernel<<<(E + 255) / 256, 256>>>(eidx, E);
    zero_hist_kernel<<<(N + 255) / 256, 256>>>(N);
    hist_kernel<<<(E + 255) / 256, 256>>>(E);
    scan_kernel<<<1, 1024>>>(N);
    scatter_kernel<<<(E + 255) / 256, 256>>>(E);
    node_pq_kernel<<<(N + 31) / 32, 256>>>(xyz, feat, W1, b1, N);
    init_kernel<<<(n4 + 255) / 256, 256>>>((uint4*)out, n4);

    int Twarp = (E + 31) >> 5;
    int grid = 4 * 148;  // persistent, 4 CTAs/SM
    if (grid > (Twarp + 3) / 4) grid = (Twarp + 3) / 4;
    edge_mma_kernel<<<grid, 128>>>(W2, b2, out, E);

    finalize_kernel<<<(n4 + 255) / 256, 256>>>((uint4*)out, n4);
}

// round 8
// speedup vs baseline: 1.0527x; 1.0527x over previous
#include <cuda_runtime.h>
#include <cuda_fp16.h>
#include <math.h>
#include <stdint.h>

#define NMAX 100000
#define EMAX 1700000
#define FULLM 0xffffffffu

// Scratch: per-node P (cols 0..63, includes b1) and Q (cols 64..127). 51.2 MB.
__device__ float g_PQ[(size_t)NMAX * 128];
__device__ int2 g_edges[EMAX];  // packed (src, dst) as int32
__device__ int g_is64;

__device__ __forceinline__ uint32_t smem_u32(const void* p) {
    uint32_t a;
    asm("{ .reg .u64 t; cvta.to.shared.u64 t, %1; cvt.u32.u64 %0, t; }"
        : "=r"(a) : "l"(p));
    return a;
}

// m16n8k16 row.col f32 += f16*f16
__device__ __forceinline__ void mma16816(float* c, const uint32_t* a,
                                         const uint32_t* b) {
    asm volatile(
        "mma.sync.aligned.m16n8k16.row.col.f32.f16.f16.f32 "
        "{%0,%1,%2,%3}, {%4,%5,%6,%7}, {%8,%9}, {%0,%1,%2,%3};"
        : "+f"(c[0]), "+f"(c[1]), "+f"(c[2]), "+f"(c[3])
        : "r"(a[0]), "r"(a[1]), "r"(a[2]), "r"(a[3]), "r"(b[0]), "r"(b[1]));
}

__device__ __forceinline__ void ldmatrix_x4(uint32_t* r, uint32_t addr) {
    asm volatile(
        "ldmatrix.sync.aligned.m8n8.x4.shared.b16 {%0,%1,%2,%3}, [%4];"
        : "=r"(r[0]), "=r"(r[1]), "=r"(r[2]), "=r"(r[3]) : "r"(addr));
}

// ===========================================================================
// Detect int64 vs int32 edge_index (jax x64-disabled emits int32).
// ===========================================================================
__global__ void detect_kernel(const unsigned int* __restrict__ ei) {
    __shared__ int any;
    if (threadIdx.x == 0) any = 0;
    __syncthreads();
    if (ei[2 * threadIdx.x + 1] != 0u) any = 1;  // benign race
    __syncthreads();
    if (threadIdx.x == 0) g_is64 = (any == 0) ? 1 : 0;
}

__global__ void conv_edges_kernel(const void* __restrict__ eidx, int E) {
    int i = blockIdx.x * blockDim.x + threadIdx.x;
    if (i >= E) return;
    int s, d;
    if (g_is64) {
        const long long* e64 = (const long long*)eidx;
        s = (int)e64[i];
        d = (int)e64[E + i];
    } else {
        const int* e32 = (const int*)eidx;
        s = e32[i];
        d = e32[E + i];
    }
    g_edges[i] = make_int2(s, d);
}

// ===========================================================================
// Node kernel: PQ[n] = [ x@(W1a-W1b)+b1 | x@W1b ],  x = [feat(64) | xyz(3)]
// ===========================================================================
__global__ __launch_bounds__(256) void node_pq_kernel(
    const float* __restrict__ xyz, const float* __restrict__ feat,
    const float* __restrict__ W1, const float* __restrict__ b1, int N) {
    __shared__ float ws[67][128];
    __shared__ float xs[32][68];

    int tid = threadIdx.x;
    for (int i = tid; i < 67 * 128; i += 256) {
        int k = i >> 7, c = i & 127;
        float w1b = W1[(k + 67) * 64 + (c & 63)];
        ws[k][c] = (c < 64) ? (W1[k * 64 + c] - w1b) : w1b;
    }
    int n0 = blockIdx.x * 32;
    for (int i = tid; i < 32 * 67; i += 256) {
        int n = i / 67, k = i - n * 67;
        int gn = n0 + n;
        float v = 0.f;
        if (gn < N) v = (k < 64) ? feat[(size_t)gn * 64 + k]
                                 : xyz[(size_t)gn * 3 + (k - 64)];
        xs[n][k] = v;
    }
    __syncthreads();

    int cg = tid & 31, ng = tid >> 5;
    int c0 = cg * 4, nr = ng * 4;
    float acc[4][4];
#pragma unroll
    for (int i = 0; i < 4; i++)
#pragma unroll
        for (int j = 0; j < 4; j++)
            acc[i][j] = (c0 < 64) ? b1[c0 + j] : 0.f;

#pragma unroll 67
    for (int k = 0; k < 67; k++) {
        float4 w = *(const float4*)&ws[k][c0];
#pragma unroll
        for (int i = 0; i < 4; i++) {
            float xv = xs[nr + i][k];
            acc[i][0] = fmaf(xv, w.x, acc[i][0]);
            acc[i][1] = fmaf(xv, w.y, acc[i][1]);
            acc[i][2] = fmaf(xv, w.z, acc[i][2]);
            acc[i][3] = fmaf(xv, w.w, acc[i][3]);
        }
    }
#pragma unroll
    for (int i = 0; i < 4; i++) {
        int gn = n0 + nr + i;
        if (gn < N) {
            float4 v = make_float4(acc[i][0], acc[i][1], acc[i][2], acc[i][3]);
            *(float4*)&g_PQ[(size_t)gn * 128 + c0] = v;
        }
    }
}

// ===========================================================================
// Init output to -inf bits (vectorized); finalize -inf -> 0
// ===========================================================================
__global__ void init_kernel(uint4* __restrict__ out, int n4) {
    int i = blockIdx.x * blockDim.x + threadIdx.x;
    if (i < n4)
        out[i] = make_uint4(0xff800000u, 0xff800000u, 0xff800000u, 0xff800000u);
}

__global__ void finalize_kernel(uint4* __restrict__ out, int n4) {
    int i = blockIdx.x * blockDim.x + threadIdx.x;
    if (i >= n4) return;
    uint4 v = out[i];
    bool ch = false;
    if (v.x == 0xff800000u) { v.x = 0u; ch = true; }
    if (v.y == 0xff800000u) { v.y = 0u; ch = true; }
    if (v.z == 0xff800000u) { v.z = 0u; ch = true; }
    if (v.w == 0xff800000u) { v.w = 0u; ch = true; }
    if (ch) out[i] = v;
}

// ===========================================================================
// Float atomic max via int/uint ordering trick.
// ===========================================================================
__device__ __forceinline__ void atomic_max_f(float* a, float v) {
    if (v >= 0.f)
        atomicMax((int*)a, __float_as_int(v));
    else
        atomicMin((unsigned int*)a, __float_as_uint(v));
}

// ===========================================================================
// Edge HMMA kernel, v5: cooperative gather + 2-term fp16 MMA.
// Persistent CTAs, 128 threads = 4 independent warps, 4 CTAs/SM.
// Per warp-tile (32 edges):
//   Gather: lanes 0-15 load edge 2g's full 256B P/Q rows cooperatively,
//           lanes 16-31 edge 2g+1's (each LDG.128 -> only 4 cache lines).
//   z = relu(P[dst]+Q[src]); split z = zh + zl (both fp16, 22 mantissa bits)
//   Y = zh@W + zl@W  with W in single fp16 (mma.sync m16n8k16 f16, fp32
//   accum, b2 in C-init). Error ~ z@(W - fp16(W)) ~ 1.4e-4 rel (norm).
//   scatter-max into out[dst] with monotonic-safe pre-checked atomics.
// ===========================================================================
__global__ __launch_bounds__(128, 4) void edge_mma_kernel(
    const float* __restrict__ W2, const float* __restrict__ b2,
    float* __restrict__ out, int E) {
    __shared__ char zbuf[4][8192];  // per warp: zh 4KB + zl 4KB
    __shared__ char wtile[8192];    // W2^T fp16 (64 rows n x 128B k)

    const int tid = threadIdx.x;
    const int lane = tid & 31;
    const int wid = tid >> 5;

    // ---- build swizzled W2^T fp16 in SMEM (once per CTA) ----
    for (int i = tid; i < 64 * 64; i += 128) {
        int n = i >> 6, k = i & 63;
        float w = W2[k * 64 + n];
        uint32_t off = (uint32_t)n * 128 + (((uint32_t)(2 * k)) ^ ((uint32_t)(n & 7) << 4));
        *(__half*)(&wtile[off]) = __float2half_rn(w);
    }
    __syncthreads();

    const uint32_t zh_base = smem_u32(&zbuf[wid][0]);
    const uint32_t zl_base = zh_base + 4096;
    const uint32_t w_base = smem_u32(&wtile[0]);

    // B-frag ldmatrix lane addressing (covers ks pair per x4)
    const uint32_t brow = lane & 7;
    const uint32_t bswz = brow << 4;
    const uint32_t bpart = (((uint32_t)lane >> 3) & 1) * 16 + (((uint32_t)lane >> 4) & 1) * 32;
    const uint32_t boff0 = brow * 128 + (bpart ^ bswz);        // ks0,ks1
    const uint32_t boff1 = brow * 128 + ((bpart + 64) ^ bswz); // ks2,ks3

    // A-frag ldmatrix lane addressing
    const int am = lane >> 3, rowin = lane & 7;
    const uint32_t lswz = (uint32_t)rowin << 4;
    const uint32_t akb = (uint32_t)((am >> 1) << 4);
    const int arow_in = ((am & 1) << 3) + rowin;

    const int rsel = lane >> 2;
    const int colb = (lane & 3) * 2;

    // b2 pairs register-resident
    float2 b2v[8];
#pragma unroll
    for (int nt = 0; nt < 8; nt++)
        b2v[nt] = *(const float2*)(b2 + nt * 8 + colb);

    // cooperative-gather lane pieces
    const int sub = lane >> 4;               // which edge of the pair
    const int cq = lane & 15;                // column quad (4 floats)
    const uint32_t cbyte = (uint32_t)cq * 8; // byte offset in fp16 row

    const int T = (E + 31) >> 5;
    const int gw = blockIdx.x * 4 + wid;
    const int nw = gridDim.x * 4;

    if (gw >= T) return;

    int t = gw;
    int e0 = t * 32 + lane;
    int2 sd = g_edges[(e0 < E) ? e0 : 0];

    for (; t < T; t += nw) {
        int e = t * 32 + lane;
        bool valid = (e < E);
        int mydst = valid ? sd.y : -1;

        __syncwarp();  // prior tile's ldmatrix reads done before overwrite

        // ---- cooperative gather + relu + fp16 hi/lo split -> SMEM ----
#pragma unroll 4
        for (int g = 0; g < 16; g++) {
            int esel = 2 * g + sub;
            int d = __shfl_sync(FULLM, sd.y, esel);
            int s = __shfl_sync(FULLM, sd.x, esel);
            float4 p = *((const float4*)(g_PQ + (size_t)d * 128) + cq);
            float4 q = *((const float4*)(g_PQ + (size_t)s * 128 + 64) + cq);
            float z0 = fmaxf(p.x + q.x, 0.f), z1 = fmaxf(p.y + q.y, 0.f);
            float z2 = fmaxf(p.z + q.z, 0.f), z3 = fmaxf(p.w + q.w, 0.f);
            __half2 h01 = __floats2half2_rn(z0, z1);
            __half2 h23 = __floats2half2_rn(z2, z3);
            float2 f01 = __half22float2(h01);
            float2 f23 = __half22float2(h23);
            __half2 l01 = __floats2half2_rn(z0 - f01.x, z1 - f01.y);
            __half2 l23 = __floats2half2_rn(z2 - f23.x, z3 - f23.y);
            uint32_t row = (uint32_t)(2 * g + sub);
            uint32_t off = row * 128 + (cbyte ^ ((row & 7) << 4));
            asm volatile("st.shared.v2.b32 [%0], {%1,%2};"
                         :: "r"(zh_base + off),
                            "r"(*(uint32_t*)&h01), "r"(*(uint32_t*)&h23));
            asm volatile("st.shared.v2.b32 [%0], {%1,%2};"
                         :: "r"(zl_base + off),
                            "r"(*(uint32_t*)&l01), "r"(*(uint32_t*)&l23));
        }
        __syncwarp();

        // ---- prefetch next tile's edge record (hides L2 latency) ----
        int tn = t + nw;
        if (tn < T) {
            int en = tn * 32 + lane;
            sd = g_edges[(en < E) ? en : 0];
        }

#pragma unroll
        for (int mt = 0; mt < 2; mt++) {
            // A fragments for this 16-row slice (zh + zl, 4 k-steps)
            uint32_t ah[4][4], al[4][4];
            uint32_t rowb = (uint32_t)(mt * 16 + arow_in) * 128;
#pragma unroll
            for (int ks = 0; ks < 4; ks++) {
                uint32_t off = rowb + (((uint32_t)ks * 32 + akb) ^ lswz);
                ldmatrix_x4(ah[ks], zh_base + off);
                ldmatrix_x4(al[ks], zl_base + off);
            }

            int d0 = __shfl_sync(FULLM, mydst, mt * 16 + rsel);
            int d1 = __shfl_sync(FULLM, mydst, mt * 16 + 8 + rsel);
            const float* pc0 = out + (size_t)(d0 < 0 ? 0 : d0) * 64;
            const float* pc1 = out + (size_t)(d1 < 0 ? 0 : d1) * 64;

#pragma unroll
            for (int nt = 0; nt < 8; nt++) {
                int col = nt * 8 + colb;
                // issue long-latency loads first; MMAs below cover them
                float2 cur0 = *(const float2*)(pc0 + col);
                float2 cur1 = *(const float2*)(pc1 + col);

                uint32_t bw[4][2];
                uint32_t wb = (uint32_t)nt * 1024;
                ldmatrix_x4(&bw[0][0], w_base + wb + boff0);
                ldmatrix_x4(&bw[2][0], w_base + wb + boff1);

                float c[4] = {b2v[nt].x, b2v[nt].y, b2v[nt].x, b2v[nt].y};
#pragma unroll
                for (int ks = 0; ks < 4; ks++) mma16816(c, ah[ks], bw[ks]);
#pragma unroll
                for (int ks = 0; ks < 4; ks++) mma16816(c, al[ks], bw[ks]);

                if (d0 >= 0) {
                    float* o = out + (size_t)d0 * 64 + col;
                    if (c[0] > cur0.x) atomic_max_f(o, c[0]);
                    if (c[1] > cur0.y) atomic_max_f(o + 1, c[1]);
                }
                if (d1 >= 0) {
                    float* o = out + (size_t)d1 * 64 + col;
                    if (c[2] > cur1.x) atomic_max_f(o, c[2]);
                    if (c[3] > cur1.y) atomic_max_f(o + 1, c[3]);
                }
            }
        }
    }
}

// ===========================================================================
// Inputs: [0]=xyz (N*3 f32), [1]=feat (N*64 f32), [2]=edge_index (2*E int),
//         [3]=W1 (134*64 f32), [4]=b1 (64), [5]=W2 (64*64), [6]=b2 (64)
// ===========================================================================
extern "C" void kernel_launch(void* const* d_in, const int* in_sizes, int n_in,
                              void* d_out, int out_size) {
    const float* xyz  = (const float*)d_in[0];
    const float* feat = (const float*)d_in[1];
    const void*  eidx = d_in[2];
    const float* W1   = (const float*)d_in[3];
    const float* b1   = (const float*)d_in[4];
    const float* W2   = (const float*)d_in[5];
    const float* b2   = (const float*)d_in[6];
    float* out = (float*)d_out;

    int N = in_sizes[0] / 3;
    int E = in_sizes[2] / 2;
    int outn = N * 64;
    int n4 = outn / 4;

    detect_kernel<<<1, 1024>>>((const unsigned int*)eidx);
    conv_edges_kernel<<<(E + 255) / 256, 256>>>(eidx, E);
    node_pq_kernel<<<(N + 31) / 32, 256>>>(xyz, feat, W1, b1, N);
    init_kernel<<<(n4 + 255) / 256, 256>>>((uint4*)out, n4);

    int Twarp = (E + 31) >> 5;
    int grid = 4 * 148;  // persistent, 4 CTAs/SM
    if (grid > (Twarp + 3) / 4) grid = (Twarp + 3) / 4;
    edge_mma_kernel<<<grid, 128>>>(W2, b2, out, E);

    finalize_kernel<<<(n4 + 255) / 256, 256>>>((uint4*)out, n4);
}